// round 11
// baseline (speedup 1.0000x reference)
#include <cuda_runtime.h>

// Problem constants (match reference)
#define BATCH   512
#define IN_DIM  784
#define OUT_DIM 10
#define STEPS   200
#define NSCAN   (STEPS - 1)              // 199 drive entries / scan steps
#define TC      32                       // time-chunk size
#define NCHUNK  ((NSCAN + TC - 1) / TC)  // 7
#define NG      16                       // i-groups (one warp each)
#define IPG     (IN_DIM / NG)            // 49 inputs per warp = 12 quads + 1

// LIF constants
#define A_M     0.995f                   // 1 - DT/TAU_M
#define G_M     0.005f                   // DT/TAU_M
#define A_S     0.98f                    // 1 - DT/TAU_S

__device__ __forceinline__ float ldg(const float* p) {
    float v;
    asm volatile("ld.global.f32 %0, [%1];" : "=f"(v) : "l"(p));
    return v;
}

__global__ __launch_bounds__(512, 4)
void snn_kernel(const float* __restrict__ x,     // [B, IN, STEPS]
                const float* __restrict__ w,     // [O, IN]
                float* __restrict__ out)         // [B, O]
{
    __shared__ __align__(16) float wsh[OUT_DIM * IN_DIM]; // [o][i] (gmem layout), 31360 B
    __shared__ float drvp[8][TC * OUT_DIM];               // partial drives, 10240 B
    __shared__ int   done_sh;

    const int b   = blockIdx.x;
    const int tid = threadIdx.x;
    const int g   = tid >> 5;            // warp id = i-group
    const int tl  = tid & 31;            // lane: t-owner in phase B; loader role in A

    // Weights: pure coalesced float4 copy, identical layout in smem.
    {
        const float4* w4  = (const float4*)w;
        float4*       ws4 = (float4*)wsh;
        #pragma unroll
        for (int k = tid; k < (OUT_DIM * IN_DIM) / 4; k += 512)
            ws4[k] = w4[k];
    }
    if (tid == 0) done_sh = 0;
    // No sync here — the sync before first consume covers it.

    const float* xb = x + (size_t)b * IN_DIM * STEPS;

    // LIF state for threads 0..9 (persists across chunks)
    float V = 0.0f, I = 0.0f;
    int   fst = 0;
    const int ibase = g * IPG;

    // Loader-role constants (fixed per lane): row subgroup + t-quad
    const int rsub = tl >> 3;            // 0..3: row offset within quad group
    const int tq   = tl & 7;             // t-quad: covers t0 + 4*tq .. +3
    // Extraction constants (t-owner role)
    const int kown = tl & 3;             // which ballot
    const int qsh  = tl >> 2;            // shift into ballot

    for (int c = 0; c < NCHUNK; c++) {
        const int t0   = c * TC;
        const int tcur = t0 + tl;        // drive index this lane owns in phase B

        // ---- Phase A: 12 x LDG.128 (4 rows x 32 t each) + ballot transpose ----
        unsigned m0 = 0u, m1 = 0u;       // bit j -> i = ibase + j (m1: j+32)
        const bool ldok = (t0 + 4 * tq) <= (STEPS - 4);   // float4 fully in-memory
        const float4* xq = (const float4*)(xb + (size_t)(ibase + rsub) * STEPS + t0 + 4 * tq);

        #pragma unroll 4
        for (int it = 0; it < 12; it++) {
            float4 v = make_float4(0.f, 0.f, 0.f, 0.f);
            if (ldok) v = xq[(size_t)it * STEPS];         // +4 rows per it (STEPS floats = 1 row; float4 idx)
            unsigned balA = __ballot_sync(0xFFFFFFFFu, v.x != 0.0f);
            unsigned balB = __ballot_sync(0xFFFFFFFFu, v.y != 0.0f);
            unsigned balC = __ballot_sync(0xFFFFFFFFu, v.z != 0.0f);
            unsigned balD = __ballot_sync(0xFFFFFFFFu, v.w != 0.0f);
            unsigned s1  = (kown & 1) ? balB : balA;
            unsigned s2  = (kown & 1) ? balD : balC;
            unsigned bal = (kown & 2) ? s2 : s1;
            unsigned wd  = bal >> qsh;
            unsigned nib = (wd & 1u) | ((wd >> 7) & 2u) | ((wd >> 14) & 4u) | ((wd >> 21) & 8u);
            if (4 * it < 32) m0 |= nib << (4 * it);
            else             m1 |= nib << (4 * it - 32);
        }
        // Remainder row 48 (scalar, lane = t)
        if (tcur < NSCAN) {
            float vr = ldg(xb + (size_t)(ibase + 48) * STEPS + tcur);
            if (__float_as_uint(vr) != 0u) m1 |= (1u << 16);
        } else {
            m0 = 0u; m1 = 0u;            // this lane's t is out of range: no drive
        }

        if (c == 0) __syncthreads();     // uniform; weights now visible

        // ---- Phase B: dense mask walk (~1 set bit/thread on average) ----
        float acc[OUT_DIM];
        #pragma unroll
        for (int o = 0; o < OUT_DIM; o++) acc[o] = 0.0f;
        while (m0) {
            int j = __ffs(m0) - 1;
            m0 &= m0 - 1;
            const float* wr = &wsh[ibase + j];
            #pragma unroll
            for (int o = 0; o < OUT_DIM; o++) acc[o] += wr[o * IN_DIM];
        }
        while (m1) {
            int j = __ffs(m1) - 1;
            m1 &= m1 - 1;
            const float* wr = &wsh[ibase + 32 + j];
            #pragma unroll
            for (int o = 0; o < OUT_DIM; o++) acc[o] += wr[o * IN_DIM];
        }

        // ---- reduce 16 partials -> 8 -> 1 ----
        float* dp = &drvp[g & 7][tl * OUT_DIM];
        if (g >= 8) {
            #pragma unroll
            for (int o = 0; o < OUT_DIM; o++) dp[o] = acc[o];
        }
        __syncthreads();
        if (g < 8) {
            #pragma unroll
            for (int o = 0; o < OUT_DIM; o++) dp[o] += acc[o];
        }
        __syncthreads();
        if (tid < TC * OUT_DIM) {        // 320 threads: one (t,o) each
            float s = drvp[0][tid];
            #pragma unroll
            for (int q = 1; q < 8; q++) s += drvp[q][tid];
            drvp[0][tid] = s;
        }
        __syncthreads();

        // ---- incremental LIF scan by threads 0..9 ----
        if (tid < OUT_DIM) {
            const int o    = tid;
            const int tend = min(TC, NSCAN - t0);
            if (fst == 0) {
                for (int tt = 0; tt < tend; tt++) {
                    float Vn = A_M * V + G_M * I;
                    float In = A_S * I + drvp[0][tt * OUT_DIM + o];
                    if (Vn > 1.0f) { fst = t0 + tt + 1; break; }
                    V = Vn;
                    I = In;
                }
            }
            unsigned m = __ballot_sync(0x3FFu, fst != 0);
            if (tid == 0 && m == 0x3FFu) done_sh = 1;
        }
        __syncthreads();
        if (done_sh) break;              // all 10 neurons spiked: rest of x[b] is dead
    }

    if (tid < OUT_DIM)
        out[b * OUT_DIM + tid] = (fst == 0) ? (float)(STEPS - 1) : (float)fst;
}

extern "C" void kernel_launch(void* const* d_in, const int* in_sizes, int n_in,
                              void* d_out, int out_size)
{
    const float* x = (const float*)d_in[0];   // [512, 784, 200]
    const float* w = (const float*)d_in[1];   // [10, 784]
    float* out = (float*)d_out;               // [512, 10]
    snn_kernel<<<BATCH, 512>>>(x, w, out);
}